// round 2
// baseline (speedup 1.0000x reference)
#include <cuda_runtime.h>

#define NN 100000
#define EE 1600000
#define FIN 128
#define HID 64

// ---- scratch (static __device__ — no allocation) ----
__device__ __align__(16) float g_h1[NN * HID];
__device__ __align__(16) float g_as1[NN * 4];
__device__ __align__(16) float g_ad1[NN * 4];
__device__ __align__(16) float g_agg1[NN * HID];
__device__ __align__(16) float g_h2[NN * HID];
__device__ __align__(16) float g_as2[NN];
__device__ __align__(16) float g_ad2[NN];
__device__ int g_cnt[NN];    // degree by dst
__device__ int g_rs[NN];     // CSR row starts (exclusive scan of cnt)
__device__ int g_cur[NN];    // fill cursors
__device__ int g_srcs[EE];   // CSR: src node per incident edge, grouped by dst
__device__ int g_part[128];  // scan partials

__device__ __forceinline__ float lrelu(float t) { return t > 0.f ? t : 0.2f * t; }

// ---------------- CSR build ----------------
__global__ void k_zero_cnt() {
    int i = blockIdx.x * blockDim.x + threadIdx.x;
    if (i < NN) g_cnt[i] = 0;
}

__global__ void k_hist(const int* __restrict__ ei) {
    int e = blockIdx.x * blockDim.x + threadIdx.x;
    if (e < EE) atomicAdd(&g_cnt[__ldg(&ei[EE + e])], 1);
}

// block-level exclusive scan (1024 threads/block)
__global__ void k_scan1() {
    __shared__ int sh[32];
    int i = blockIdx.x * 1024 + threadIdx.x;
    int lane = threadIdx.x & 31, w = threadIdx.x >> 5;
    int v = (i < NN) ? g_cnt[i] : 0;
    int s = v;
#pragma unroll
    for (int off = 1; off < 32; off <<= 1) {
        int t = __shfl_up_sync(0xffffffffu, s, off);
        if (lane >= off) s += t;
    }
    if (lane == 31) sh[w] = s;
    __syncthreads();
    if (w == 0) {
        int t = sh[lane];
#pragma unroll
        for (int off = 1; off < 32; off <<= 1) {
            int u = __shfl_up_sync(0xffffffffu, t, off);
            if (lane >= off) t += u;
        }
        sh[lane] = t;
    }
    __syncthreads();
    int base = (w > 0) ? sh[w - 1] : 0;
    if (i < NN) g_rs[i] = base + s - v;  // exclusive within block
    if (threadIdx.x == 1023) g_part[blockIdx.x] = base + s;  // block total
}

// scan the (<=128) block partials in one block
__global__ void k_scan2(int nparts) {
    __shared__ int sh[4];
    int lane = threadIdx.x & 31, w = threadIdx.x >> 5;
    int v = (threadIdx.x < nparts) ? g_part[threadIdx.x] : 0;
    int s = v;
#pragma unroll
    for (int off = 1; off < 32; off <<= 1) {
        int t = __shfl_up_sync(0xffffffffu, s, off);
        if (lane >= off) s += t;
    }
    if (lane == 31) sh[w] = s;
    __syncthreads();
    int base = 0;
    for (int k = 0; k < w; k++) base += sh[k];
    if (threadIdx.x < nparts) g_part[threadIdx.x] = base + s - v;  // exclusive
}

__global__ void k_scan3() {
    int i = blockIdx.x * blockDim.x + threadIdx.x;
    if (i < NN) {
        int r = g_rs[i] + g_part[i >> 10];
        g_rs[i] = r;
        g_cur[i] = r;
    }
}

__global__ void k_fill(const int* __restrict__ ei) {
    int e = blockIdx.x * blockDim.x + threadIdx.x;
    if (e < EE) {
        int s = __ldg(&ei[e]);
        int d = __ldg(&ei[EE + e]);
        int p = atomicAdd(&g_cur[d], 1);
        g_srcs[p] = s;
    }
}

// ---------------- layer-1 GEMM: h1 = x @ W1, + per-head attention dots ----------------
__global__ void k_gemm1(const float* __restrict__ x, const float* __restrict__ W1,
                        const float* __restrict__ a_src, const float* __restrict__ a_dst) {
    __shared__ float Wsh[FIN * HID];
    int tid = threadIdx.x;
    for (int i = tid; i < FIN * HID; i += 256) Wsh[i] = W1[i];
    __syncthreads();

    int lane = tid & 31, w = tid >> 5;
    int r0 = (blockIdx.x * 8 + w) * 4;

    float xr[4][4];
#pragma unroll
    for (int i = 0; i < 4; i++)
#pragma unroll
        for (int j = 0; j < 4; j++)
            xr[i][j] = x[(r0 + i) * FIN + 32 * j + lane];

    float acc[4][2] = {};
#pragma unroll
    for (int k = 0; k < FIN; k++) {
        float w0 = Wsh[k * HID + lane];
        float w1 = Wsh[k * HID + lane + 32];
#pragma unroll
        for (int i = 0; i < 4; i++) {
            float xk = __shfl_sync(0xffffffffu, xr[i][k >> 5], k & 31);
            acc[i][0] += xk * w0;
            acc[i][1] += xk * w1;
        }
    }

    float al = __ldg(&a_src[lane]), ah = __ldg(&a_src[lane + 32]);
    float dl = __ldg(&a_dst[lane]), dh = __ldg(&a_dst[lane + 32]);

#pragma unroll
    for (int i = 0; i < 4; i++) {
        int row = r0 + i;
        g_h1[row * HID + lane] = acc[i][0];
        g_h1[row * HID + lane + 32] = acc[i][1];
        // feature `lane` -> head lane>>4 (0/1); feature lane+32 -> head 2+(lane>>4)
        float pa0 = acc[i][0] * al, pa1 = acc[i][1] * ah;
        float pd0 = acc[i][0] * dl, pd1 = acc[i][1] * dh;
#pragma unroll
        for (int off = 8; off; off >>= 1) {
            pa0 += __shfl_xor_sync(0xffffffffu, pa0, off);
            pa1 += __shfl_xor_sync(0xffffffffu, pa1, off);
            pd0 += __shfl_xor_sync(0xffffffffu, pd0, off);
            pd1 += __shfl_xor_sync(0xffffffffu, pd1, off);
        }
        if ((lane & 15) == 0) {
            int hh = lane >> 4;
            g_as1[row * 4 + hh] = pa0;
            g_as1[row * 4 + 2 + hh] = pa1;
            g_ad1[row * 4 + hh] = pd0;
            g_ad1[row * 4 + 2 + hh] = pd1;
        }
    }
}

// ---------------- layer-1 gather aggregation: one warp per dst node ----------------
// Fused softmax: out[n] = sum_e exp(lrelu(t_e)) * h1[src_e] / (sum_e exp(lrelu(t_e)) + eps)
__global__ void k_agg1() {
    int n = blockIdx.x * 8 + (threadIdx.x >> 5);
    if (n >= NN) return;
    int lane = threadIdx.x & 31;
    int head = lane >> 3;  // 8 lanes (16 features) per head

    int rs = g_rs[n];
    int deg = g_cnt[n];
    float adv = g_ad1[n * 4 + head];

    const float2* h1v = (const float2*)g_h1;
    float ax = 0.f, ay = 0.f, den = 0.f;

    int j = 0;
    for (; j + 2 <= deg; j += 2) {
        int s0 = g_srcs[rs + j];
        int s1 = g_srcs[rs + j + 1];
        float t0 = g_as1[s0 * 4 + head] + adv;
        float t1 = g_as1[s1 * 4 + head] + adv;
        float2 v0 = h1v[s0 * 32 + lane];
        float2 v1 = h1v[s1 * 32 + lane];
        float e0 = __expf(lrelu(t0));
        float e1 = __expf(lrelu(t1));
        den += e0 + e1;
        ax += e0 * v0.x + e1 * v1.x;
        ay += e0 * v0.y + e1 * v1.y;
    }
    if (j < deg) {
        int s0 = g_srcs[rs + j];
        float t0 = g_as1[s0 * 4 + head] + adv;
        float2 v0 = h1v[s0 * 32 + lane];
        float e0 = __expf(lrelu(t0));
        den += e0;
        ax += e0 * v0.x;
        ay += e0 * v0.y;
    }
    float inv = 1.f / (den + 1e-16f);
    float2 o;
    o.x = ax * inv;
    o.y = ay * inv;
    ((float2*)g_agg1)[n * 32 + lane] = o;
}

// ---------------- layer-2 GEMM: h2 = relu(agg1 + b1) @ W2, + attention dots (1 head) ----------------
__global__ void k_gemm2(const float* __restrict__ W2, const float* __restrict__ b1,
                        const float* __restrict__ a_src, const float* __restrict__ a_dst) {
    __shared__ float Wsh[HID * HID];
    int tid = threadIdx.x;
    for (int i = tid; i < HID * HID; i += 256) Wsh[i] = W2[i];
    __syncthreads();

    int lane = tid & 31, w = tid >> 5;
    int r0 = (blockIdx.x * 8 + w) * 4;
    float bl = __ldg(&b1[lane]), bh = __ldg(&b1[lane + 32]);

    float xr[4][2];
#pragma unroll
    for (int i = 0; i < 4; i++) {
        xr[i][0] = fmaxf(g_agg1[(r0 + i) * 64 + lane] + bl, 0.f);
        xr[i][1] = fmaxf(g_agg1[(r0 + i) * 64 + lane + 32] + bh, 0.f);
    }

    float acc[4][2] = {};
#pragma unroll
    for (int k = 0; k < HID; k++) {
        float w0 = Wsh[k * HID + lane];
        float w1 = Wsh[k * HID + lane + 32];
#pragma unroll
        for (int i = 0; i < 4; i++) {
            float xk = __shfl_sync(0xffffffffu, xr[i][k >> 5], k & 31);
            acc[i][0] += xk * w0;
            acc[i][1] += xk * w1;
        }
    }

    float al = __ldg(&a_src[lane]), ah = __ldg(&a_src[lane + 32]);
    float dl = __ldg(&a_dst[lane]), dh = __ldg(&a_dst[lane + 32]);

#pragma unroll
    for (int i = 0; i < 4; i++) {
        int row = r0 + i;
        g_h2[row * HID + lane] = acc[i][0];
        g_h2[row * HID + lane + 32] = acc[i][1];
        float pa = acc[i][0] * al + acc[i][1] * ah;
        float pd = acc[i][0] * dl + acc[i][1] * dh;
#pragma unroll
        for (int off = 16; off; off >>= 1) {
            pa += __shfl_xor_sync(0xffffffffu, pa, off);
            pd += __shfl_xor_sync(0xffffffffu, pd, off);
        }
        if (lane == 0) {
            g_as2[row] = pa;
            g_ad2[row] = pd;
        }
    }
}

// ---------------- layer-2 gather aggregation fused with final projection ----------------
__global__ void k_agg2f(const float* __restrict__ b2, const float* __restrict__ Wc,
                        const float* __restrict__ bc, float* __restrict__ out) {
    int n = blockIdx.x * 8 + (threadIdx.x >> 5);
    if (n >= NN) return;
    int lane = threadIdx.x & 31;

    int rs = g_rs[n];
    int deg = g_cnt[n];
    float adv = g_ad2[n];

    const float2* h2v = (const float2*)g_h2;
    float ax = 0.f, ay = 0.f, den = 0.f;

    int j = 0;
    for (; j + 2 <= deg; j += 2) {
        int s0 = g_srcs[rs + j];
        int s1 = g_srcs[rs + j + 1];
        float t0 = g_as2[s0] + adv;
        float t1 = g_as2[s1] + adv;
        float2 v0 = h2v[s0 * 32 + lane];
        float2 v1 = h2v[s1 * 32 + lane];
        float e0 = __expf(lrelu(t0));
        float e1 = __expf(lrelu(t1));
        den += e0 + e1;
        ax += e0 * v0.x + e1 * v1.x;
        ay += e0 * v0.y + e1 * v1.y;
    }
    if (j < deg) {
        int s0 = g_srcs[rs + j];
        float t0 = g_as2[s0] + adv;
        float2 v0 = h2v[s0 * 32 + lane];
        float e0 = __expf(lrelu(t0));
        den += e0;
        ax += e0 * v0.x;
        ay += e0 * v0.y;
    }
    float inv = 1.f / (den + 1e-16f);
    // final: out[n] = sum_c relu(agg2[c] + b2[c]) * Wc[c] + bc
    float v = fmaxf(ax * inv + __ldg(&b2[2 * lane]), 0.f) * __ldg(&Wc[2 * lane])
            + fmaxf(ay * inv + __ldg(&b2[2 * lane + 1]), 0.f) * __ldg(&Wc[2 * lane + 1]);
#pragma unroll
    for (int off = 16; off; off >>= 1) v += __shfl_xor_sync(0xffffffffu, v, off);
    if (lane == 0) out[n] = v + __ldg(&bc[0]);
}

extern "C" void kernel_launch(void* const* d_in, const int* in_sizes, int n_in,
                              void* d_out, int out_size) {
    const float* x      = (const float*)d_in[0];
    const int* ei       = (const int*)d_in[1];   // JAX x64 disabled -> int32
    const float* W1     = (const float*)d_in[2];
    const float* a_src1 = (const float*)d_in[3];
    const float* a_dst1 = (const float*)d_in[4];
    const float* b1     = (const float*)d_in[5];
    const float* W2     = (const float*)d_in[6];
    const float* a_src2 = (const float*)d_in[7];
    const float* a_dst2 = (const float*)d_in[8];
    const float* b2     = (const float*)d_in[9];
    const float* Wc     = (const float*)d_in[10];
    const float* bc     = (const float*)d_in[11];
    float* out          = (float*)d_out;
    (void)in_sizes; (void)n_in; (void)out_size;

    const int nparts = (NN + 1023) / 1024;  // 98

    // CSR build (by destination)
    k_zero_cnt<<<(NN + 255) / 256, 256>>>();
    k_hist<<<(EE + 255) / 256, 256>>>(ei);
    k_scan1<<<nparts, 1024>>>();
    k_scan2<<<1, 128>>>(nparts);
    k_scan3<<<(NN + 255) / 256, 256>>>();
    k_fill<<<(EE + 255) / 256, 256>>>(ei);

    // layer 1
    k_gemm1<<<3125, 256>>>(x, W1, a_src1, a_dst1);
    k_agg1<<<12500, 256>>>();

    // layer 2 + final projection
    k_gemm2<<<3125, 256>>>(W2, b1, a_src2, a_dst2);
    k_agg2f<<<12500, 256>>>(b2, Wc, bc, out);
}

// round 4
// speedup vs baseline: 1.0401x; 1.0401x over previous
#include <cuda_runtime.h>
#include <cuda_fp16.h>

#define NN 100000
#define EE 1600000
#define FIN 128
#define HID 64

// ---- scratch (static __device__ — no allocation) ----
__device__ __align__(16) __half2 g_h1h[NN * 32];  // h1, fp16, feature pairs
__device__ __align__(16) __half2 g_h2h[NN * 32];  // h2, fp16
__device__ __align__(16) float g_as1[NN * 4];
__device__ __align__(16) float g_ad1[NN * 4];
__device__ __align__(16) float g_agg1[NN * HID];
__device__ __align__(16) float g_as2[NN];
__device__ __align__(16) float g_ad2[NN];
__device__ int g_cnt[NN];    // degree by dst
__device__ int g_rs[NN];     // CSR row starts
__device__ int g_cur[NN];    // fill cursors
__device__ int g_srcs[EE];   // CSR: src per incident edge, grouped by dst
__device__ int g_part[128];  // scan partials

__device__ __forceinline__ float lrelu(float t) { return t > 0.f ? t : 0.2f * t; }

// ---------------- CSR build ----------------
__global__ void k_zero_cnt() {
    int i = blockIdx.x * blockDim.x + threadIdx.x;
    if (i < NN) g_cnt[i] = 0;
}

__global__ void k_hist(const int* __restrict__ ei) {
    int e = blockIdx.x * blockDim.x + threadIdx.x;
    if (e < EE) atomicAdd(&g_cnt[__ldg(&ei[EE + e])], 1);
}

__global__ void k_scan1() {
    __shared__ int sh[32];
    int i = blockIdx.x * 1024 + threadIdx.x;
    int lane = threadIdx.x & 31, w = threadIdx.x >> 5;
    int v = (i < NN) ? g_cnt[i] : 0;
    int s = v;
#pragma unroll
    for (int off = 1; off < 32; off <<= 1) {
        int t = __shfl_up_sync(0xffffffffu, s, off);
        if (lane >= off) s += t;
    }
    if (lane == 31) sh[w] = s;
    __syncthreads();
    if (w == 0) {
        int t = sh[lane];
#pragma unroll
        for (int off = 1; off < 32; off <<= 1) {
            int u = __shfl_up_sync(0xffffffffu, t, off);
            if (lane >= off) t += u;
        }
        sh[lane] = t;
    }
    __syncthreads();
    int base = (w > 0) ? sh[w - 1] : 0;
    if (i < NN) g_rs[i] = base + s - v;
    if (threadIdx.x == 1023) g_part[blockIdx.x] = base + s;
}

__global__ void k_scan2(int nparts) {
    __shared__ int sh[4];
    int lane = threadIdx.x & 31, w = threadIdx.x >> 5;
    int v = (threadIdx.x < nparts) ? g_part[threadIdx.x] : 0;
    int s = v;
#pragma unroll
    for (int off = 1; off < 32; off <<= 1) {
        int t = __shfl_up_sync(0xffffffffu, s, off);
        if (lane >= off) s += t;
    }
    if (lane == 31) sh[w] = s;
    __syncthreads();
    int base = 0;
    for (int k = 0; k < w; k++) base += sh[k];
    if (threadIdx.x < nparts) g_part[threadIdx.x] = base + s - v;
}

__global__ void k_scan3() {
    int i = blockIdx.x * blockDim.x + threadIdx.x;
    if (i < NN) {
        int r = g_rs[i] + g_part[i >> 10];
        g_rs[i] = r;
        g_cur[i] = r;
    }
}

__global__ void k_fill(const int* __restrict__ ei) {
    int e = blockIdx.x * blockDim.x + threadIdx.x;
    if (e < EE) {
        int s = __ldg(&ei[e]);
        int d = __ldg(&ei[EE + e]);
        int p = atomicAdd(&g_cur[d], 1);
        g_srcs[p] = s;
    }
}

// ---------------- layer-1 GEMM: h1 = x @ W1 (fp16 out) + per-head attention dots ----------------
// Lane owns adjacent feature pair (2*lane, 2*lane+1); head = lane>>3.
__global__ void k_gemm1(const float* __restrict__ x, const float* __restrict__ W1,
                        const float* __restrict__ a_src, const float* __restrict__ a_dst) {
    __shared__ float2 Wsh[FIN * 32];
    int tid = threadIdx.x;
    for (int i = tid; i < FIN * 32; i += 256) Wsh[i] = ((const float2*)W1)[i];
    __syncthreads();

    int lane = tid & 31, w = tid >> 5;
    int r0 = (blockIdx.x * 8 + w) * 4;

    float xr[4][4];
#pragma unroll
    for (int i = 0; i < 4; i++)
#pragma unroll
        for (int j = 0; j < 4; j++)
            xr[i][j] = x[(r0 + i) * FIN + 32 * j + lane];

    float acc0[4] = {}, acc1[4] = {};
#pragma unroll
    for (int k = 0; k < FIN; k++) {
        float2 wv = Wsh[k * 32 + lane];
#pragma unroll
        for (int i = 0; i < 4; i++) {
            float xk = __shfl_sync(0xffffffffu, xr[i][k >> 5], k & 31);
            acc0[i] += xk * wv.x;
            acc1[i] += xk * wv.y;
        }
    }

    float s0 = __ldg(&a_src[2 * lane]), s1 = __ldg(&a_src[2 * lane + 1]);
    float d0 = __ldg(&a_dst[2 * lane]), d1 = __ldg(&a_dst[2 * lane + 1]);

#pragma unroll
    for (int i = 0; i < 4; i++) {
        int row = r0 + i;
        g_h1h[row * 32 + lane] = __floats2half2_rn(acc0[i], acc1[i]);
        float pa = acc0[i] * s0 + acc1[i] * s1;
        float pd = acc0[i] * d0 + acc1[i] * d1;
#pragma unroll
        for (int off = 4; off; off >>= 1) {
            pa += __shfl_xor_sync(0xffffffffu, pa, off);
            pd += __shfl_xor_sync(0xffffffffu, pd, off);
        }
        if ((lane & 7) == 0) {
            g_as1[row * 4 + (lane >> 3)] = pa;
            g_ad1[row * 4 + (lane >> 3)] = pd;
        }
    }
}

// ---------------- layer-1 gather aggregation: one warp per dst node ----------------
__global__ void k_agg1() {
    int n = blockIdx.x * 8 + (threadIdx.x >> 5);
    if (n >= NN) return;
    int lane = threadIdx.x & 31;
    int head = lane >> 3;

    int rs = g_rs[n];
    int deg = g_cnt[n];
    float adv = g_ad1[n * 4 + head];

    float ax = 0.f, ay = 0.f, den = 0.f;

    int j = 0;
    for (; j + 4 <= deg; j += 4) {
        int s0 = g_srcs[rs + j],     s1 = g_srcs[rs + j + 1];
        int s2 = g_srcs[rs + j + 2], s3 = g_srcs[rs + j + 3];
        float t0 = g_as1[s0 * 4 + head] + adv;
        float t1 = g_as1[s1 * 4 + head] + adv;
        float t2 = g_as1[s2 * 4 + head] + adv;
        float t3 = g_as1[s3 * 4 + head] + adv;
        float2 v0 = __half22float2(g_h1h[s0 * 32 + lane]);
        float2 v1 = __half22float2(g_h1h[s1 * 32 + lane]);
        float2 v2 = __half22float2(g_h1h[s2 * 32 + lane]);
        float2 v3 = __half22float2(g_h1h[s3 * 32 + lane]);
        float e0 = __expf(lrelu(t0)), e1 = __expf(lrelu(t1));
        float e2 = __expf(lrelu(t2)), e3 = __expf(lrelu(t3));
        den += (e0 + e1) + (e2 + e3);
        ax += e0 * v0.x + e1 * v1.x + e2 * v2.x + e3 * v3.x;
        ay += e0 * v0.y + e1 * v1.y + e2 * v2.y + e3 * v3.y;
    }
    for (; j < deg; j++) {
        int s0 = g_srcs[rs + j];
        float t0 = g_as1[s0 * 4 + head] + adv;
        float2 v0 = __half22float2(g_h1h[s0 * 32 + lane]);
        float e0 = __expf(lrelu(t0));
        den += e0;
        ax += e0 * v0.x;
        ay += e0 * v0.y;
    }
    float inv = 1.f / (den + 1e-16f);
    float2 o;
    o.x = ax * inv;
    o.y = ay * inv;
    ((float2*)g_agg1)[n * 32 + lane] = o;
}

// ---------------- layer-2 GEMM: h2 = relu(agg1 + b1) @ W2 (fp16 out) + dots (1 head) ----------------
__global__ void k_gemm2(const float* __restrict__ W2, const float* __restrict__ b1,
                        const float* __restrict__ a_src, const float* __restrict__ a_dst) {
    __shared__ float2 Wsh[HID * 32];
    int tid = threadIdx.x;
    for (int i = tid; i < HID * 32; i += 256) Wsh[i] = ((const float2*)W2)[i];
    __syncthreads();

    int lane = tid & 31, w = tid >> 5;
    int r0 = (blockIdx.x * 8 + w) * 4;
    float b0 = __ldg(&b1[2 * lane]), b1v = __ldg(&b1[2 * lane + 1]);

    float2 xr[4];
#pragma unroll
    for (int i = 0; i < 4; i++) {
        float2 v = ((const float2*)g_agg1)[(r0 + i) * 32 + lane];
        xr[i].x = fmaxf(v.x + b0, 0.f);
        xr[i].y = fmaxf(v.y + b1v, 0.f);
    }

    float acc0[4] = {}, acc1[4] = {};
#pragma unroll
    for (int k = 0; k < HID; k++) {
        float2 wv = Wsh[k * 32 + lane];
#pragma unroll
        for (int i = 0; i < 4; i++) {
            float xk = __shfl_sync(0xffffffffu, (k & 1) ? xr[i].y : xr[i].x, k >> 1);
            acc0[i] += xk * wv.x;
            acc1[i] += xk * wv.y;
        }
    }

    float s0 = __ldg(&a_src[2 * lane]), s1 = __ldg(&a_src[2 * lane + 1]);
    float d0 = __ldg(&a_dst[2 * lane]), d1 = __ldg(&a_dst[2 * lane + 1]);

#pragma unroll
    for (int i = 0; i < 4; i++) {
        int row = r0 + i;
        g_h2h[row * 32 + lane] = __floats2half2_rn(acc0[i], acc1[i]);
        float pa = acc0[i] * s0 + acc1[i] * s1;
        float pd = acc0[i] * d0 + acc1[i] * d1;
#pragma unroll
        for (int off = 16; off; off >>= 1) {
            pa += __shfl_xor_sync(0xffffffffu, pa, off);
            pd += __shfl_xor_sync(0xffffffffu, pd, off);
        }
        if (lane == 0) {
            g_as2[row] = pa;
            g_ad2[row] = pd;
        }
    }
}

// ---------------- layer-2 gather aggregation fused with final projection ----------------
__global__ void k_agg2f(const float* __restrict__ b2, const float* __restrict__ Wc,
                        const float* __restrict__ bc, float* __restrict__ out) {
    int n = blockIdx.x * 8 + (threadIdx.x >> 5);
    if (n >= NN) return;
    int lane = threadIdx.x & 31;

    int rs = g_rs[n];
    int deg = g_cnt[n];
    float adv = g_ad2[n];

    float ax = 0.f, ay = 0.f, den = 0.f;

    int j = 0;
    for (; j + 4 <= deg; j += 4) {
        int s0 = g_srcs[rs + j],     s1 = g_srcs[rs + j + 1];
        int s2 = g_srcs[rs + j + 2], s3 = g_srcs[rs + j + 3];
        float t0 = g_as2[s0] + adv, t1 = g_as2[s1] + adv;
        float t2 = g_as2[s2] + adv, t3 = g_as2[s3] + adv;
        float2 v0 = __half22float2(g_h2h[s0 * 32 + lane]);
        float2 v1 = __half22float2(g_h2h[s1 * 32 + lane]);
        float2 v2 = __half22float2(g_h2h[s2 * 32 + lane]);
        float2 v3 = __half22float2(g_h2h[s3 * 32 + lane]);
        float e0 = __expf(lrelu(t0)), e1 = __expf(lrelu(t1));
        float e2 = __expf(lrelu(t2)), e3 = __expf(lrelu(t3));
        den += (e0 + e1) + (e2 + e3);
        ax += e0 * v0.x + e1 * v1.x + e2 * v2.x + e3 * v3.x;
        ay += e0 * v0.y + e1 * v1.y + e2 * v2.y + e3 * v3.y;
    }
    for (; j < deg; j++) {
        int s0 = g_srcs[rs + j];
        float t0 = g_as2[s0] + adv;
        float2 v0 = __half22float2(g_h2h[s0 * 32 + lane]);
        float e0 = __expf(lrelu(t0));
        den += e0;
        ax += e0 * v0.x;
        ay += e0 * v0.y;
    }
    float inv = 1.f / (den + 1e-16f);
    float v = fmaxf(ax * inv + __ldg(&b2[2 * lane]), 0.f) * __ldg(&Wc[2 * lane])
            + fmaxf(ay * inv + __ldg(&b2[2 * lane + 1]), 0.f) * __ldg(&Wc[2 * lane + 1]);
#pragma unroll
    for (int off = 16; off; off >>= 1) v += __shfl_xor_sync(0xffffffffu, v, off);
    if (lane == 0) out[n] = v + __ldg(&bc[0]);
}

extern "C" void kernel_launch(void* const* d_in, const int* in_sizes, int n_in,
                              void* d_out, int out_size) {
    const float* x      = (const float*)d_in[0];
    const int* ei       = (const int*)d_in[1];   // JAX x64 disabled -> int32
    const float* W1     = (const float*)d_in[2];
    const float* a_src1 = (const float*)d_in[3];
    const float* a_dst1 = (const float*)d_in[4];
    const float* b1     = (const float*)d_in[5];
    const float* W2     = (const float*)d_in[6];
    const float* a_src2 = (const float*)d_in[7];
    const float* a_dst2 = (const float*)d_in[8];
    const float* b2     = (const float*)d_in[9];
    const float* Wc     = (const float*)d_in[10];
    const float* bc     = (const float*)d_in[11];
    float* out          = (float*)d_out;
    (void)in_sizes; (void)n_in; (void)out_size;

    const int nparts = (NN + 1023) / 1024;  // 98

    k_zero_cnt<<<(NN + 255) / 256, 256>>>();
    k_hist<<<(EE + 255) / 256, 256>>>(ei);
    k_scan1<<<nparts, 1024>>>();
    k_scan2<<<1, 128>>>(nparts);
    k_scan3<<<(NN + 255) / 256, 256>>>();
    k_fill<<<(EE + 255) / 256, 256>>>(ei);

    k_gemm1<<<3125, 256>>>(x, W1, a_src1, a_dst1);
    k_agg1<<<12500, 256>>>();

    k_gemm2<<<3125, 256>>>(W2, b1, a_src2, a_dst2);
    k_agg2f<<<12500, 256>>>(b2, Wc, bc, out);
}